// round 7
// baseline (speedup 1.0000x reference)
#include <cuda_runtime.h>
#include <math.h>

#define TT 1024
#define BB 32
#define DD 1024
#define BD (BB*DD)          /* 32768    */
#define TBD (TT*BB*DD)      /* 33554432 */

/* ---------- packed f32x2 helpers (sm_103a FFMA2) ---------- */
__device__ __forceinline__ void fma2(unsigned long long& acc,
                                     unsigned long long a,
                                     unsigned long long b) {
    asm("fma.rn.f32x2 %0, %1, %2, %0;" : "+l"(acc) : "l"(a), "l"(b));
}
__device__ __forceinline__ unsigned long long pack2(float lo, float hi) {
    unsigned long long r;
    asm("mov.b64 %0, {%1, %2};" : "=l"(r)
        : "r"(__float_as_uint(lo)), "r"(__float_as_uint(hi)));
    return r;
}
__device__ __forceinline__ float lo32(unsigned long long v) {
    return __uint_as_float((unsigned int)(v & 0xffffffffull));
}
__device__ __forceinline__ float hi32(unsigned long long v) {
    return __uint_as_float((unsigned int)(v >> 32));
}

/* ---------- acquire/release flag ops ---------- */
__device__ __forceinline__ unsigned int ld_acq(const unsigned int* p) {
    unsigned int v;
    asm volatile("ld.acquire.gpu.global.b32 %0, [%1];" : "=r"(v) : "l"(p));
    return v;
}
__device__ __forceinline__ void st_rel(unsigned int* p, unsigned int v) {
    asm volatile("st.release.gpu.global.b32 [%0], %1;" :: "l"(p), "r"(v) : "memory");
}

/* transposed hidden state, double-buffered: g_hT[par][k][b], 256 KB static */
__device__ float g_hT[2][DD][BB];
__device__ unsigned int g_flags[128];
__device__ unsigned int g_bar = 0;
__device__ unsigned int g_gen = 0;

/* ================= precompute GEMM (FFMA2) =================
 * C[m,n] = sum_k x[m,k]*W[n,k] + bias[n], m<32768, n<2048
 *   n <  1024 : W=R_x,     bias=b,       dst = out section    (stash xRx[t])
 *   n >= 1024 : W=W_delta, bias=b_delta, dst = h section +BD  (stash xWd[t])
 * W staged in smem as pre-packed (w,w) pairs -> no pack2 in the inner loop.
 */
#define BM 64
#define BN 64
#define BKK 16
#define PAD 72

__global__ __launch_bounds__(256) void pre_gemm_kernel(
    const float* __restrict__ x,
    const float* __restrict__ Rx,
    const float* __restrict__ Wdl,
    const float* __restrict__ bias_v,
    const float* __restrict__ bias_d,
    float* __restrict__ outsec,
    float* __restrict__ hsec)
{
    __shared__ float As[BKK][PAD];
    __shared__ unsigned long long Wp[BKK][BN];

    const int m0  = blockIdx.x * BM;
    const int n0g = blockIdx.y * BN;
    const int sel = (n0g >= DD) ? 1 : 0;
    const float* __restrict__ W    = sel ? Wdl    : Rx;
    const float* __restrict__ bias = sel ? bias_d : bias_v;
    float* __restrict__ dst = sel ? (hsec + BD) : outsec;
    const int n0 = n0g & (DD - 1);

    const int tid  = threadIdx.x;
    const int lrow = tid >> 2;
    const int lk4  = (tid & 3) * 4;
    const int tx   = tid & 15;          /* n dir */
    const int ty   = tid >> 4;          /* m dir */

    unsigned long long acc2[2][4];
    #pragma unroll
    for (int p = 0; p < 2; p++)
        #pragma unroll
        for (int j = 0; j < 4; j++) acc2[p][j] = 0ull;

    const float* xa = x + (size_t)(m0 + lrow) * DD;
    const float* wa = W + (size_t)(n0 + lrow) * DD;

    for (int kk = 0; kk < DD; kk += BKK) {
        float4 a4 = *(const float4*)(xa + kk + lk4);
        float4 w4 = *(const float4*)(wa + kk + lk4);
        As[lk4 + 0][lrow] = a4.x; As[lk4 + 1][lrow] = a4.y;
        As[lk4 + 2][lrow] = a4.z; As[lk4 + 3][lrow] = a4.w;
        Wp[lk4 + 0][lrow] = pack2(w4.x, w4.x);
        Wp[lk4 + 1][lrow] = pack2(w4.y, w4.y);
        Wp[lk4 + 2][lrow] = pack2(w4.z, w4.z);
        Wp[lk4 + 3][lrow] = pack2(w4.w, w4.w);
        __syncthreads();

        #pragma unroll
        for (int k = 0; k < BKK; k++) {
            ulonglong2 a2 = *(const ulonglong2*)&As[k][ty * 4];
            ulonglong2 wA = *(const ulonglong2*)&Wp[k][tx * 4];
            ulonglong2 wB = *(const ulonglong2*)&Wp[k][tx * 4 + 2];
            fma2(acc2[0][0], a2.x, wA.x); fma2(acc2[0][1], a2.x, wA.y);
            fma2(acc2[0][2], a2.x, wB.x); fma2(acc2[0][3], a2.x, wB.y);
            fma2(acc2[1][0], a2.y, wA.x); fma2(acc2[1][1], a2.y, wA.y);
            fma2(acc2[1][2], a2.y, wB.x); fma2(acc2[1][3], a2.y, wB.y);
        }
        __syncthreads();
    }

    #pragma unroll
    for (int p = 0; p < 2; p++) {
        #pragma unroll
        for (int j = 0; j < 4; j++) {
            const int col = n0 + tx * 4 + j;
            const float bb = bias[col];
            dst[(size_t)(m0 + ty * 4 + 2 * p + 0) * DD + col] = lo32(acc2[p][j]) + bb;
            dst[(size_t)(m0 + ty * 4 + 2 * p + 1) * DD + col] = hi32(acc2[p][j]) + bb;
        }
    }
}

/* ================= persistent recurrence =================
 * 128 CTAs x 256 threads, all co-resident. CTA c owns d-slice [8c,8c+8)
 * for ALL b. Weights (64 KB) smem-resident, loaded once. h kept in the
 * transposed double-buffered g_hT. Per-step cross-CTA sync = distributed
 * flag barrier: CTA releases g_flags[cta]=t+1; wait = 128 threads each
 * acquire-poll one flag in parallel. Stash operands for step t+1 are
 * prefetched into registers during the wait; h_prev lives in a register.
 */
#define SRSTRIDE 36
#define SMEM_W   (DD * 8 * 8)                        /* 65536 B packed w  */
#define SMEM_R   (16 * 8 * SRSTRIDE * 4)             /* 18432 B reduction */
#define SMEM_REC (SMEM_W + SMEM_R)

__device__ __forceinline__ void init_grid_sync() {
    __syncthreads();
    if (threadIdx.x == 0) {
        __threadfence();
        unsigned int gen = *((volatile unsigned int*)&g_gen);
        if (atomicAdd(&g_bar, 1) == 127u) {
            atomicExch(&g_bar, 0);
            __threadfence();
            atomicAdd(&g_gen, 1);
        } else {
            while (*((volatile unsigned int*)&g_gen) == gen) __nanosleep(32);
        }
        __threadfence();
    }
    __syncthreads();
}

__global__ __launch_bounds__(256, 1) void rec_kernel(
    const float* __restrict__ x,
    const float* __restrict__ h0,
    const float* __restrict__ Rh,
    const float* __restrict__ Rd,
    const float* __restrict__ bgate,
    float* __restrict__ outsec,
    float* __restrict__ hsec)
{
    extern __shared__ unsigned char smem[];
    unsigned long long* sWp = (unsigned long long*)smem;   /* [k][8] pairs */
    float* sRed = (float*)(smem + SMEM_W);

    const int cta  = blockIdx.x;
    const int d0   = cta * 8;
    const int tid  = threadIdx.x;
    const int w    = tid >> 5;
    const int lane = tid & 31;

    /* ---- stage packed weight pairs into smem (once) ---- */
    #pragma unroll
    for (int m = 0; m < 2; m++) {
        const float* W = m ? Rd : Rh;
        #pragma unroll
        for (int p = 0; p < 4; p++) {
            const float* r0 = W + (size_t)(d0 + 2 * p)     * DD;
            const float* r1 = W + (size_t)(d0 + 2 * p + 1) * DD;
            for (int k = tid; k < DD; k += 256)
                sWp[k * 8 + m * 4 + p] = pack2(r0[k], r1[k]);
        }
    }

    /* ---- init transposed h[0]; reset this CTA's flag ---- */
    g_hT[0][8 * cta + w][lane] = h0[(size_t)lane * DD + 8 * cta + w];
    if (tid == 0) g_flags[cta] = 0u;

    const int kb  = w * 128;
    const int edl = tid & 7;        /* epilogue d-local */
    const int eb  = tid >> 3;       /* epilogue b       */
    const float bgv = bgate[d0 + edl];

    /* register-resident state + first-step stash prefetch */
    float hp   = h0[(size_t)eb * DD + d0 + edl];
    size_t idx = (size_t)eb * DD + d0 + edl;     /* idx for t=0 */
    float pf_v = outsec[idx];
    float pf_d = hsec[idx + BD];
    float pf_x = x[idx];

    init_grid_sync();   /* hT[0] + flag resets visible; weights staged */

    for (int t = 0; t < TT; t++) {
        const int cur = t & 1, nxt = cur ^ 1;
        const float* hcol = &g_hT[cur][0][lane];

        unsigned long long av0 = 0, av1 = 0, av2 = 0, av3 = 0;
        unsigned long long ad0 = 0, ad1 = 0, ad2 = 0, ad3 = 0;

        float hbuf[8];
        #pragma unroll
        for (int i = 0; i < 8; i++)
            hbuf[i] = __ldcg(hcol + (size_t)(kb + i) * 32);

        #pragma unroll
        for (int g = 0; g < 16; g++) {
            float hnx[8];
            if (g < 15) {
                #pragma unroll
                for (int i = 0; i < 8; i++)
                    hnx[i] = __ldcg(hcol + (size_t)(kb + (g + 1) * 8 + i) * 32);
            }
            #pragma unroll
            for (int i = 0; i < 8; i++) {
                const int k = kb + g * 8 + i;
                unsigned long long h2 = pack2(hbuf[i], hbuf[i]);
                ulonglong2 wv0 = *(const ulonglong2*)&sWp[k * 8 + 0];
                ulonglong2 wv1 = *(const ulonglong2*)&sWp[k * 8 + 2];
                ulonglong2 wd0 = *(const ulonglong2*)&sWp[k * 8 + 4];
                ulonglong2 wd1 = *(const ulonglong2*)&sWp[k * 8 + 6];
                fma2(av0, wv0.x, h2); fma2(av1, wv0.y, h2);
                fma2(av2, wv1.x, h2); fma2(av3, wv1.y, h2);
                fma2(ad0, wd0.x, h2); fma2(ad1, wd0.y, h2);
                fma2(ad2, wd1.x, h2); fma2(ad3, wd1.y, h2);
            }
            if (g < 15) {
                #pragma unroll
                for (int i = 0; i < 8; i++) hbuf[i] = hnx[i];
            }
        }

        /* stage per-warp partials: sRed[(w*2+m)*8 + d][b] */
        {
            float* r0 = sRed + ((w * 2 + 0) * 8) * SRSTRIDE + lane;
            float* r1 = sRed + ((w * 2 + 1) * 8) * SRSTRIDE + lane;
            r0[0 * SRSTRIDE] = lo32(av0); r0[1 * SRSTRIDE] = hi32(av0);
            r0[2 * SRSTRIDE] = lo32(av1); r0[3 * SRSTRIDE] = hi32(av1);
            r0[4 * SRSTRIDE] = lo32(av2); r0[5 * SRSTRIDE] = hi32(av2);
            r0[6 * SRSTRIDE] = lo32(av3); r0[7 * SRSTRIDE] = hi32(av3);
            r1[0 * SRSTRIDE] = lo32(ad0); r1[1 * SRSTRIDE] = hi32(ad0);
            r1[2 * SRSTRIDE] = lo32(ad1); r1[3 * SRSTRIDE] = hi32(ad1);
            r1[4 * SRSTRIDE] = lo32(ad2); r1[5 * SRSTRIDE] = hi32(ad2);
            r1[6 * SRSTRIDE] = lo32(ad3); r1[7 * SRSTRIDE] = hi32(ad3);
        }
        __syncthreads();

        /* ---- elementwise epilogue (all operands already in regs) ---- */
        {
            float sumv = 0.f, sumd = 0.f;
            #pragma unroll
            for (int kw = 0; kw < 8; kw++) {
                sumv += sRed[((kw * 2 + 0) * 8 + edl) * SRSTRIDE + eb];
                sumd += sRed[((kw * 2 + 1) * 8 + edl) * SRSTRIDE + eb];
            }
            const float v     = pf_v + sumv;
            const float dpre  = pf_d + sumd;
            const float delta = 1.f / (1.f + __expf(-dpre));
            const float hn    = (1.f - delta) * hp + delta * tanhf(v);
            const float z     = hn + pf_x + bgv;
            const float sig   = 1.f / (1.f + __expf(-z));

            outsec[idx]             = hn * z * sig;   /* out[t]            */
            hsec[idx + BD]          = hn;             /* h[t+1] (output)   */
            g_hT[nxt][d0 + edl][eb] = hn;             /* h[t+1] transposed */
            hp = hn;
        }

        /* ---- publish h[t+1] ---- */
        __threadfence();
        __syncthreads();                       /* also guards sRed reuse */
        if (tid == 0) st_rel(&g_flags[cta], (unsigned int)(t + 1));

        if (t + 1 < TT) {
            /* prefetch next step's stash while the barrier settles */
            idx += BD;
            pf_v = __ldcg(outsec + idx);
            pf_d = __ldcg(hsec + idx + BD);
            pf_x = __ldcg(x + idx);

            /* distributed wait: thread i polls flag i */
            const unsigned int tgt = (unsigned int)(t + 1);
            if (tid < 128) {
                while (ld_acq(&g_flags[tid]) < tgt) { }
            }
            __syncthreads();
            __threadfence();   /* order h reads after observed release */
        }
    }
}

extern "C" void kernel_launch(void* const* d_in, const int* in_sizes, int n_in,
                              void* d_out, int out_size)
{
    const float* x   = (const float*)d_in[0];
    const float* h0  = (const float*)d_in[1];
    const float* Rh  = (const float*)d_in[2];
    const float* Rx  = (const float*)d_in[3];
    const float* Rd  = (const float*)d_in[4];
    const float* Wdl = (const float*)d_in[5];
    const float* b   = (const float*)d_in[6];
    const float* bd  = (const float*)d_in[7];
    const float* bgt = (const float*)d_in[8];

    float* outsec = (float*)d_out;          /* [T,B,D] outputs         */
    float* hsec   = outsec + (size_t)TBD;   /* [T+1,B,D] hidden states */

    cudaFuncSetAttribute(rec_kernel,
                         cudaFuncAttributeMaxDynamicSharedMemorySize,
                         (int)SMEM_REC);

    /* h[0] = h0 */
    cudaMemcpyAsync(hsec, h0, (size_t)BD * sizeof(float),
                    cudaMemcpyDeviceToDevice, 0);

    /* big input GEMM: stash xRx into out[t], xWd into h[t+1] */
    dim3 pgrid(TT * BB / BM, 2 * DD / BN);  /* (512, 32) */
    pre_gemm_kernel<<<pgrid, 256>>>(x, Rx, Wdl, b, bd, outsec, hsec);

    /* single persistent kernel for the whole scan */
    rec_kernel<<<128, 256, SMEM_REC>>>(x, h0, Rh, Rd, bgt, outsec, hsec);
}

// round 8
// speedup vs baseline: 1.1712x; 1.1712x over previous
#include <cuda_runtime.h>
#include <math.h>

#define TT 1024
#define BB 32
#define DD 1024
#define BD (BB*DD)          /* 32768    */
#define TBD (TT*BB*DD)      /* 33554432 */

/* ---------- packed f32x2 helpers (sm_103a FFMA2) ---------- */
__device__ __forceinline__ void fma2(unsigned long long& acc,
                                     unsigned long long a,
                                     unsigned long long b) {
    asm("fma.rn.f32x2 %0, %1, %2, %0;" : "+l"(acc) : "l"(a), "l"(b));
}
__device__ __forceinline__ unsigned long long pack2(float lo, float hi) {
    unsigned long long r;
    asm("mov.b64 %0, {%1, %2};" : "=l"(r)
        : "r"(__float_as_uint(lo)), "r"(__float_as_uint(hi)));
    return r;
}
__device__ __forceinline__ float lo32(unsigned long long v) {
    return __uint_as_float((unsigned int)(v & 0xffffffffull));
}
__device__ __forceinline__ float hi32(unsigned long long v) {
    return __uint_as_float((unsigned int)(v >> 32));
}
__device__ __forceinline__ float tanh_fast(float x) {
    float y;
    asm("tanh.approx.f32 %0, %1;" : "=f"(y) : "f"(x));
    return y;
}

/* transposed hidden state, double-buffered: g_hT[par][k][b], 256 KB static */
__device__ float g_hT[2][DD][BB];

/* barrier state: group counters padded to distinct L2 slices */
__device__ unsigned int g_cnt[8 * 64];      /* use g_cnt[g*64] */
__device__ unsigned int g_root = 0;
__device__ unsigned int g_gen2 = 0;         /* monotonic step generation */
__device__ unsigned int g_bar = 0;          /* init barrier */
__device__ unsigned int g_gen = 0;

/* ================= precompute GEMM (FFMA2) ================= */
#define BM 64
#define BN 64
#define BKK 16
#define PAD 72

__global__ __launch_bounds__(256) void pre_gemm_kernel(
    const float* __restrict__ x,
    const float* __restrict__ Rx,
    const float* __restrict__ Wdl,
    const float* __restrict__ bias_v,
    const float* __restrict__ bias_d,
    float* __restrict__ outsec,
    float* __restrict__ hsec)
{
    __shared__ float As[BKK][PAD];
    __shared__ unsigned long long Wp[BKK][BN];

    const int m0  = blockIdx.x * BM;
    const int n0g = blockIdx.y * BN;
    const int sel = (n0g >= DD) ? 1 : 0;
    const float* __restrict__ W    = sel ? Wdl    : Rx;
    const float* __restrict__ bias = sel ? bias_d : bias_v;
    float* __restrict__ dst = sel ? (hsec + BD) : outsec;
    const int n0 = n0g & (DD - 1);

    const int tid  = threadIdx.x;
    const int lrow = tid >> 2;
    const int lk4  = (tid & 3) * 4;
    const int tx   = tid & 15;
    const int ty   = tid >> 4;

    unsigned long long acc2[2][4];
    #pragma unroll
    for (int p = 0; p < 2; p++)
        #pragma unroll
        for (int j = 0; j < 4; j++) acc2[p][j] = 0ull;

    const float* xa = x + (size_t)(m0 + lrow) * DD;
    const float* wa = W + (size_t)(n0 + lrow) * DD;

    for (int kk = 0; kk < DD; kk += BKK) {
        float4 a4 = *(const float4*)(xa + kk + lk4);
        float4 w4 = *(const float4*)(wa + kk + lk4);
        As[lk4 + 0][lrow] = a4.x; As[lk4 + 1][lrow] = a4.y;
        As[lk4 + 2][lrow] = a4.z; As[lk4 + 3][lrow] = a4.w;
        Wp[lk4 + 0][lrow] = pack2(w4.x, w4.x);
        Wp[lk4 + 1][lrow] = pack2(w4.y, w4.y);
        Wp[lk4 + 2][lrow] = pack2(w4.z, w4.z);
        Wp[lk4 + 3][lrow] = pack2(w4.w, w4.w);
        __syncthreads();

        #pragma unroll
        for (int k = 0; k < BKK; k++) {
            ulonglong2 a2 = *(const ulonglong2*)&As[k][ty * 4];
            ulonglong2 wA = *(const ulonglong2*)&Wp[k][tx * 4];
            ulonglong2 wB = *(const ulonglong2*)&Wp[k][tx * 4 + 2];
            fma2(acc2[0][0], a2.x, wA.x); fma2(acc2[0][1], a2.x, wA.y);
            fma2(acc2[0][2], a2.x, wB.x); fma2(acc2[0][3], a2.x, wB.y);
            fma2(acc2[1][0], a2.y, wA.x); fma2(acc2[1][1], a2.y, wA.y);
            fma2(acc2[1][2], a2.y, wB.x); fma2(acc2[1][3], a2.y, wB.y);
        }
        __syncthreads();
    }

    #pragma unroll
    for (int p = 0; p < 2; p++) {
        #pragma unroll
        for (int j = 0; j < 4; j++) {
            const int col = n0 + tx * 4 + j;
            const float bb = bias[col];
            dst[(size_t)(m0 + ty * 4 + 2 * p + 0) * DD + col] = lo32(acc2[p][j]) + bb;
            dst[(size_t)(m0 + ty * 4 + 2 * p + 1) * DD + col] = hi32(acc2[p][j]) + bb;
        }
    }
}

/* ================= persistent recurrence ================= */
#define SRSTRIDE 36
#define SMEM_W   (DD * 8 * 8)                        /* 65536 B packed w  */
#define SMEM_R   (16 * 8 * SRSTRIDE * 4)             /* 18432 B reduction */
#define SMEM_REC (SMEM_W + SMEM_R)

/* replay-safe init barrier (R6-proven) */
__device__ __forceinline__ void init_grid_sync() {
    __syncthreads();
    if (threadIdx.x == 0) {
        __threadfence();
        unsigned int gen = *((volatile unsigned int*)&g_gen);
        if (atomicAdd(&g_bar, 1) == 127u) {
            atomicExch(&g_bar, 0);
            __threadfence();
            atomicAdd(&g_gen, 1);
        } else {
            while (*((volatile unsigned int*)&g_gen) == gen) __nanosleep(32);
        }
        __threadfence();
    }
    __syncthreads();
}

/* per-step barrier: tree arrival (16-way groups + 8-way root), gen-poll
 * with backoff by ONE thread per CTA. base makes the gen compare relative
 * -> replay-safe with no resets (counters naturally return to 0). */
__device__ __forceinline__ void step_sync(int cta, unsigned int base,
                                          unsigned int t) {
    __syncthreads();
    if (threadIdx.x == 0) {
        __threadfence();
        if (atomicAdd(&g_cnt[(cta >> 4) * 64], 1) == 15u) {
            /* group complete: retire counter, arrive at root */
            atomicExch(&g_cnt[(cta >> 4) * 64], 0u);
            if (atomicAdd(&g_root, 1) == 7u) {
                atomicExch(&g_root, 0u);
                __threadfence();
                atomicAdd(&g_gen2, 1);
            }
        }
        while ((unsigned int)(*((volatile unsigned int*)&g_gen2) - base)
               < t + 1u)
            __nanosleep(32);
        __threadfence();
    }
    __syncthreads();
}

__global__ __launch_bounds__(256, 1) void rec_kernel(
    const float* __restrict__ x,
    const float* __restrict__ h0,
    const float* __restrict__ Rh,
    const float* __restrict__ Rd,
    const float* __restrict__ bgate,
    float* __restrict__ outsec,
    float* __restrict__ hsec)
{
    extern __shared__ unsigned char smem[];
    unsigned long long* sWp = (unsigned long long*)smem;   /* [k][8] pairs */
    float* sRed = (float*)(smem + SMEM_W);

    const int cta  = blockIdx.x;
    const int d0   = cta * 8;
    const int tid  = threadIdx.x;
    const int w    = tid >> 5;
    const int lane = tid & 31;

    /* relative gen base — read BEFORE the init barrier (replay-safe) */
    const unsigned int gbase = *((volatile unsigned int*)&g_gen2);

    /* ---- stage packed weight pairs into smem (once) ---- */
    #pragma unroll
    for (int m = 0; m < 2; m++) {
        const float* W = m ? Rd : Rh;
        #pragma unroll
        for (int p = 0; p < 4; p++) {
            const float* r0 = W + (size_t)(d0 + 2 * p)     * DD;
            const float* r1 = W + (size_t)(d0 + 2 * p + 1) * DD;
            for (int k = tid; k < DD; k += 256)
                sWp[k * 8 + m * 4 + p] = pack2(r0[k], r1[k]);
        }
    }

    /* ---- init transposed h[0] ---- */
    g_hT[0][8 * cta + w][lane] = h0[(size_t)lane * DD + 8 * cta + w];

    const int kb  = w * 128;
    const int edl = tid & 7;        /* epilogue d-local */
    const int eb  = tid >> 3;       /* epilogue b       */
    const float bgv = bgate[d0 + edl];

    /* register-resident state + first-step stash */
    float hp   = h0[(size_t)eb * DD + d0 + edl];
    size_t idx = (size_t)eb * DD + d0 + edl;     /* idx for t=0 */
    float pf_v = outsec[idx];
    float pf_d = hsec[idx + BD];
    float pf_x = x[idx];

    init_grid_sync();   /* hT[0] visible; weights staged */

    for (int t = 0; t < TT; t++) {
        const int cur = t & 1, nxt = cur ^ 1;
        const float* hcol = &g_hT[cur][0][lane];

        unsigned long long av0 = 0, av1 = 0, av2 = 0, av3 = 0;
        unsigned long long ad0 = 0, ad1 = 0, ad2 = 0, ad3 = 0;

        float hbuf[8];
        #pragma unroll
        for (int i = 0; i < 8; i++)
            hbuf[i] = __ldcg(hcol + (size_t)(kb + i) * 32);

        /* prefetch NEXT step's stash early: hides DRAM latency under FMA */
        float nv = 0.f, nd = 0.f, nx = 0.f;
        if (t + 1 < TT) {
            nv = __ldcg(outsec + idx + BD);
            nd = __ldcg(hsec + idx + 2 * (size_t)BD);
            nx = __ldcg(x + idx + BD);
        }

        #pragma unroll
        for (int g = 0; g < 16; g++) {
            float hnx[8];
            if (g < 15) {
                #pragma unroll
                for (int i = 0; i < 8; i++)
                    hnx[i] = __ldcg(hcol + (size_t)(kb + (g + 1) * 8 + i) * 32);
            }
            #pragma unroll
            for (int i = 0; i < 8; i++) {
                const int k = kb + g * 8 + i;
                unsigned long long h2 = pack2(hbuf[i], hbuf[i]);
                ulonglong2 wv0 = *(const ulonglong2*)&sWp[k * 8 + 0];
                ulonglong2 wv1 = *(const ulonglong2*)&sWp[k * 8 + 2];
                ulonglong2 wd0 = *(const ulonglong2*)&sWp[k * 8 + 4];
                ulonglong2 wd1 = *(const ulonglong2*)&sWp[k * 8 + 6];
                fma2(av0, wv0.x, h2); fma2(av1, wv0.y, h2);
                fma2(av2, wv1.x, h2); fma2(av3, wv1.y, h2);
                fma2(ad0, wd0.x, h2); fma2(ad1, wd0.y, h2);
                fma2(ad2, wd1.x, h2); fma2(ad3, wd1.y, h2);
            }
            if (g < 15) {
                #pragma unroll
                for (int i = 0; i < 8; i++) hbuf[i] = hnx[i];
            }
        }

        /* stage per-warp partials: sRed[(w*2+m)*8 + d][b] */
        {
            float* r0 = sRed + ((w * 2 + 0) * 8) * SRSTRIDE + lane;
            float* r1 = sRed + ((w * 2 + 1) * 8) * SRSTRIDE + lane;
            r0[0 * SRSTRIDE] = lo32(av0); r0[1 * SRSTRIDE] = hi32(av0);
            r0[2 * SRSTRIDE] = lo32(av1); r0[3 * SRSTRIDE] = hi32(av1);
            r0[4 * SRSTRIDE] = lo32(av2); r0[5 * SRSTRIDE] = hi32(av2);
            r0[6 * SRSTRIDE] = lo32(av3); r0[7 * SRSTRIDE] = hi32(av3);
            r1[0 * SRSTRIDE] = lo32(ad0); r1[1 * SRSTRIDE] = hi32(ad0);
            r1[2 * SRSTRIDE] = lo32(ad1); r1[3 * SRSTRIDE] = hi32(ad1);
            r1[4 * SRSTRIDE] = lo32(ad2); r1[5 * SRSTRIDE] = hi32(ad2);
            r1[6 * SRSTRIDE] = lo32(ad3); r1[7 * SRSTRIDE] = hi32(ad3);
        }
        __syncthreads();

        /* ---- elementwise epilogue (operands already in regs) ---- */
        {
            float sumv = 0.f, sumd = 0.f;
            #pragma unroll
            for (int kw = 0; kw < 8; kw++) {
                sumv += sRed[((kw * 2 + 0) * 8 + edl) * SRSTRIDE + eb];
                sumd += sRed[((kw * 2 + 1) * 8 + edl) * SRSTRIDE + eb];
            }
            const float v     = pf_v + sumv;
            const float dpre  = pf_d + sumd;
            const float delta = 1.f / (1.f + __expf(-dpre));
            const float hn    = (1.f - delta) * hp + delta * tanh_fast(v);
            const float z     = hn + pf_x + bgv;
            const float sig   = 1.f / (1.f + __expf(-z));

            outsec[idx]             = hn * z * sig;   /* out[t]            */
            hsec[idx + BD]          = hn;             /* h[t+1] (output)   */
            g_hT[nxt][d0 + edl][eb] = hn;             /* h[t+1] transposed */
            hp = hn;
        }

        if (t + 1 < TT) {
            pf_v = nv; pf_d = nd; pf_x = nx;
            idx += BD;
            step_sync(cta, gbase, (unsigned int)t);  /* publish h[t+1] */
        }
    }
}

extern "C" void kernel_launch(void* const* d_in, const int* in_sizes, int n_in,
                              void* d_out, int out_size)
{
    const float* x   = (const float*)d_in[0];
    const float* h0  = (const float*)d_in[1];
    const float* Rh  = (const float*)d_in[2];
    const float* Rx  = (const float*)d_in[3];
    const float* Rd  = (const float*)d_in[4];
    const float* Wdl = (const float*)d_in[5];
    const float* b   = (const float*)d_in[6];
    const float* bd  = (const float*)d_in[7];
    const float* bgt = (const float*)d_in[8];

    float* outsec = (float*)d_out;          /* [T,B,D] outputs         */
    float* hsec   = outsec + (size_t)TBD;   /* [T+1,B,D] hidden states */

    cudaFuncSetAttribute(rec_kernel,
                         cudaFuncAttributeMaxDynamicSharedMemorySize,
                         (int)SMEM_REC);

    /* h[0] = h0 */
    cudaMemcpyAsync(hsec, h0, (size_t)BD * sizeof(float),
                    cudaMemcpyDeviceToDevice, 0);

    /* big input GEMM: stash xRx into out[t], xWd into h[t+1] */
    dim3 pgrid(TT * BB / BM, 2 * DD / BN);  /* (512, 32) */
    pre_gemm_kernel<<<pgrid, 256>>>(x, Rx, Wdl, b, bd, outsec, hsec);

    /* single persistent kernel for the whole scan */
    rec_kernel<<<128, 256, SMEM_REC>>>(x, h0, Rh, Rd, bgt, outsec, hsec);
}

// round 9
// speedup vs baseline: 1.2973x; 1.1076x over previous
#include <cuda_runtime.h>
#include <math.h>

#define TT 1024
#define BB 32
#define DD 1024
#define BD (BB*DD)          /* 32768    */
#define TBD (TT*BB*DD)      /* 33554432 */

/* ---------- packed f32x2 helpers (sm_103a FFMA2) ---------- */
__device__ __forceinline__ void fma2(unsigned long long& acc,
                                     unsigned long long a,
                                     unsigned long long b) {
    asm("fma.rn.f32x2 %0, %1, %2, %0;" : "+l"(acc) : "l"(a), "l"(b));
}
__device__ __forceinline__ unsigned long long pack2(float lo, float hi) {
    unsigned long long r;
    asm("mov.b64 %0, {%1, %2};" : "=l"(r)
        : "r"(__float_as_uint(lo)), "r"(__float_as_uint(hi)));
    return r;
}
__device__ __forceinline__ float lo32(unsigned long long v) {
    return __uint_as_float((unsigned int)(v & 0xffffffffull));
}
__device__ __forceinline__ float hi32(unsigned long long v) {
    return __uint_as_float((unsigned int)(v >> 32));
}
__device__ __forceinline__ float tanh_fast(float x) {
    float y;
    asm("tanh.approx.f32 %0, %1;" : "=f"(y) : "f"(x));
    return y;
}
__device__ __forceinline__ unsigned int ld_acq(const unsigned int* p) {
    unsigned int v;
    asm volatile("ld.acquire.gpu.global.b32 %0, [%1];" : "=r"(v) : "l"(p));
    return v;
}

/* transposed hidden state, double-buffered: g_hT[par][k][b], 256 KB static */
__device__ float g_hT[2][DD][BB];

/* dependency counters: one per 16-CTA producer group, padded 256B apart.
 * Monotonic across graph replays (base-relative compares, no resets).   */
__device__ unsigned int g_wf[8 * 64];
/* init barrier */
__device__ unsigned int g_bar = 0;
__device__ unsigned int g_gen = 0;

/* ================= precompute GEMM (FFMA2) ================= */
#define BM 64
#define BN 64
#define BKK 16
#define PAD 72

__global__ __launch_bounds__(256) void pre_gemm_kernel(
    const float* __restrict__ x,
    const float* __restrict__ Rx,
    const float* __restrict__ Wdl,
    const float* __restrict__ bias_v,
    const float* __restrict__ bias_d,
    float* __restrict__ outsec,
    float* __restrict__ hsec)
{
    __shared__ float As[BKK][PAD];
    __shared__ unsigned long long Wp[BKK][BN];

    const int m0  = blockIdx.x * BM;
    const int n0g = blockIdx.y * BN;
    const int sel = (n0g >= DD) ? 1 : 0;
    const float* __restrict__ W    = sel ? Wdl    : Rx;
    const float* __restrict__ bias = sel ? bias_d : bias_v;
    float* __restrict__ dst = sel ? (hsec + BD) : outsec;
    const int n0 = n0g & (DD - 1);

    const int tid  = threadIdx.x;
    const int lrow = tid >> 2;
    const int lk4  = (tid & 3) * 4;
    const int tx   = tid & 15;
    const int ty   = tid >> 4;

    unsigned long long acc2[2][4];
    #pragma unroll
    for (int p = 0; p < 2; p++)
        #pragma unroll
        for (int j = 0; j < 4; j++) acc2[p][j] = 0ull;

    const float* xa = x + (size_t)(m0 + lrow) * DD;
    const float* wa = W + (size_t)(n0 + lrow) * DD;

    for (int kk = 0; kk < DD; kk += BKK) {
        float4 a4 = *(const float4*)(xa + kk + lk4);
        float4 w4 = *(const float4*)(wa + kk + lk4);
        As[lk4 + 0][lrow] = a4.x; As[lk4 + 1][lrow] = a4.y;
        As[lk4 + 2][lrow] = a4.z; As[lk4 + 3][lrow] = a4.w;
        Wp[lk4 + 0][lrow] = pack2(w4.x, w4.x);
        Wp[lk4 + 1][lrow] = pack2(w4.y, w4.y);
        Wp[lk4 + 2][lrow] = pack2(w4.z, w4.z);
        Wp[lk4 + 3][lrow] = pack2(w4.w, w4.w);
        __syncthreads();

        #pragma unroll
        for (int k = 0; k < BKK; k++) {
            ulonglong2 a2 = *(const ulonglong2*)&As[k][ty * 4];
            ulonglong2 wA = *(const ulonglong2*)&Wp[k][tx * 4];
            ulonglong2 wB = *(const ulonglong2*)&Wp[k][tx * 4 + 2];
            fma2(acc2[0][0], a2.x, wA.x); fma2(acc2[0][1], a2.x, wA.y);
            fma2(acc2[0][2], a2.x, wB.x); fma2(acc2[0][3], a2.x, wB.y);
            fma2(acc2[1][0], a2.y, wA.x); fma2(acc2[1][1], a2.y, wA.y);
            fma2(acc2[1][2], a2.y, wB.x); fma2(acc2[1][3], a2.y, wB.y);
        }
        __syncthreads();
    }

    #pragma unroll
    for (int p = 0; p < 2; p++) {
        #pragma unroll
        for (int j = 0; j < 4; j++) {
            const int col = n0 + tx * 4 + j;
            const float bb = bias[col];
            dst[(size_t)(m0 + ty * 4 + 2 * p + 0) * DD + col] = lo32(acc2[p][j]) + bb;
            dst[(size_t)(m0 + ty * 4 + 2 * p + 1) * DD + col] = hi32(acc2[p][j]) + bb;
        }
    }
}

/* ================= persistent recurrence ================= */
#define SRSTRIDE 36
#define SMEM_W   (DD * 8 * 8)                        /* 65536 B packed w  */
#define SMEM_R   (16 * 8 * SRSTRIDE * 4)             /* 18432 B reduction */
#define SMEM_REC (SMEM_W + SMEM_R)

/* replay-safe init barrier (R6-proven) */
__device__ __forceinline__ void init_grid_sync() {
    __syncthreads();
    if (threadIdx.x == 0) {
        __threadfence();
        unsigned int gen = *((volatile unsigned int*)&g_gen);
        if (atomicAdd(&g_bar, 1) == 127u) {
            atomicExch(&g_bar, 0);
            __threadfence();
            atomicAdd(&g_gen, 1);
        } else {
            while (*((volatile unsigned int*)&g_gen) == gen) __nanosleep(32);
        }
        __threadfence();
    }
    __syncthreads();
}

/* process one group of 8 k-values; PF!=0 -> prefetch group (k+16) into hb */
#define GROUP8(hb, kg, PF)                                                  \
    {                                                                       \
        _Pragma("unroll")                                                   \
        for (int i = 0; i < 8; i++) {                                       \
            const int k = (kg) + i;                                         \
            const float hv = hb[i];                                         \
            if (PF) hb[i] = __ldcg(hcol + (size_t)(k + 16) * 32);           \
            unsigned long long h2 = pack2(hv, hv);                          \
            ulonglong2 wv0 = *(const ulonglong2*)&sWp[k * 8 + 0];           \
            ulonglong2 wv1 = *(const ulonglong2*)&sWp[k * 8 + 2];           \
            ulonglong2 wd0 = *(const ulonglong2*)&sWp[k * 8 + 4];           \
            ulonglong2 wd1 = *(const ulonglong2*)&sWp[k * 8 + 6];           \
            fma2(av0, wv0.x, h2); fma2(av1, wv0.y, h2);                     \
            fma2(av2, wv1.x, h2); fma2(av3, wv1.y, h2);                     \
            fma2(ad0, wd0.x, h2); fma2(ad1, wd0.y, h2);                     \
            fma2(ad2, wd1.x, h2); fma2(ad3, wd1.y, h2);                     \
        }                                                                   \
    }

__global__ __launch_bounds__(256, 1) void rec_kernel(
    const float* __restrict__ x,
    const float* __restrict__ h0,
    const float* __restrict__ Rh,
    const float* __restrict__ Rd,
    const float* __restrict__ bgate,
    float* __restrict__ outsec,
    float* __restrict__ hsec)
{
    extern __shared__ unsigned char smem[];
    unsigned long long* sWp = (unsigned long long*)smem;   /* [k][8] pairs */
    float* sRed = (float*)(smem + SMEM_W);

    const int cta  = blockIdx.x;
    const int d0   = cta * 8;
    const int tid  = threadIdx.x;
    const int w    = tid >> 5;
    const int lane = tid & 31;

    /* this warp's dependency counter + replay base (read before ANY arrival
     * of this launch can happen — all arrivals are after init_grid_sync)  */
    const unsigned int* wfp = &g_wf[w * 64];
    const unsigned int wfbase = ld_acq(wfp);

    /* ---- stage packed weight pairs into smem (once) ---- */
    #pragma unroll
    for (int m = 0; m < 2; m++) {
        const float* W = m ? Rd : Rh;
        #pragma unroll
        for (int p = 0; p < 4; p++) {
            const float* r0 = W + (size_t)(d0 + 2 * p)     * DD;
            const float* r1 = W + (size_t)(d0 + 2 * p + 1) * DD;
            for (int k = tid; k < DD; k += 256)
                sWp[k * 8 + m * 4 + p] = pack2(r0[k], r1[k]);
        }
    }

    /* ---- init transposed h[0] ---- */
    g_hT[0][8 * cta + w][lane] = h0[(size_t)lane * DD + 8 * cta + w];

    const int kb  = w * 128;
    const int edl = tid & 7;        /* epilogue d-local */
    const int eb  = tid >> 3;       /* epilogue b       */
    const float bgv = bgate[d0 + edl];

    /* register-resident state + first-step stash */
    float hp   = h0[(size_t)eb * DD + d0 + edl];
    size_t idx = (size_t)eb * DD + d0 + edl;     /* idx for t=0 */
    float pf_v = outsec[idx];
    float pf_d = hsec[idx + BD];
    float pf_x = x[idx];

    init_grid_sync();   /* hT[0] visible; weights staged; bases read */

    for (int t = 0; t < TT; t++) {
        /* ---- per-warp dependency wait: h rows kb..kb+128 of step t are
         * ready once the 16 CTAs of group w have arrived t times ---- */
        if (t > 0) {
            const unsigned int need = wfbase + 16u * (unsigned int)t;
            if ((int)(ld_acq(wfp) - need) < 0) {
                do { __nanosleep(64); }
                while ((int)(ld_acq(wfp) - need) < 0);
            }
        }

        const int cur = t & 1, nxt = cur ^ 1;
        const float* hcol = &g_hT[cur][0][lane];

        unsigned long long av0 = 0, av1 = 0, av2 = 0, av3 = 0;
        unsigned long long ad0 = 0, ad1 = 0, ad2 = 0, ad3 = 0;

        /* fill 16-deep h pipeline (two groups in flight) */
        float hA[8], hB[8];
        #pragma unroll
        for (int i = 0; i < 8; i++) {
            hA[i] = __ldcg(hcol + (size_t)(kb + i) * 32);
            hB[i] = __ldcg(hcol + (size_t)(kb + 8 + i) * 32);
        }

        /* prefetch NEXT step's stash early: hidden under the FMA block */
        float nv = 0.f, nd = 0.f, nx = 0.f;
        if (t + 1 < TT) {
            nv = __ldcg(outsec + idx + BD);
            nd = __ldcg(hsec + idx + 2 * (size_t)BD);
            nx = __ldcg(x + idx + BD);
        }

        for (int gg = 0; gg < 7; gg++) {          /* groups 0..13 w/ pf */
            const int kg = kb + gg * 16;
            GROUP8(hA, kg, 1)
            GROUP8(hB, kg + 8, 1)
        }
        {                                          /* groups 14,15 no pf */
            const int kg = kb + 7 * 16;
            GROUP8(hA, kg, 0)
            GROUP8(hB, kg + 8, 0)
        }

        /* stage per-warp partials: sRed[(w*2+m)*8 + d][b] */
        {
            float* r0 = sRed + ((w * 2 + 0) * 8) * SRSTRIDE + lane;
            float* r1 = sRed + ((w * 2 + 1) * 8) * SRSTRIDE + lane;
            r0[0 * SRSTRIDE] = lo32(av0); r0[1 * SRSTRIDE] = hi32(av0);
            r0[2 * SRSTRIDE] = lo32(av1); r0[3 * SRSTRIDE] = hi32(av1);
            r0[4 * SRSTRIDE] = lo32(av2); r0[5 * SRSTRIDE] = hi32(av2);
            r0[6 * SRSTRIDE] = lo32(av3); r0[7 * SRSTRIDE] = hi32(av3);
            r1[0 * SRSTRIDE] = lo32(ad0); r1[1 * SRSTRIDE] = hi32(ad0);
            r1[2 * SRSTRIDE] = lo32(ad1); r1[3 * SRSTRIDE] = hi32(ad1);
            r1[4 * SRSTRIDE] = lo32(ad2); r1[5 * SRSTRIDE] = hi32(ad2);
            r1[6 * SRSTRIDE] = lo32(ad3); r1[7 * SRSTRIDE] = hi32(ad3);
        }
        __syncthreads();

        /* ---- elementwise epilogue (operands already in regs) ---- */
        {
            float sumv = 0.f, sumd = 0.f;
            #pragma unroll
            for (int kw = 0; kw < 8; kw++) {
                sumv += sRed[((kw * 2 + 0) * 8 + edl) * SRSTRIDE + eb];
                sumd += sRed[((kw * 2 + 1) * 8 + edl) * SRSTRIDE + eb];
            }
            const float v     = pf_v + sumv;
            const float dpre  = pf_d + sumd;
            const float delta = 1.f / (1.f + __expf(-dpre));
            const float hn    = (1.f - delta) * hp + delta * tanh_fast(v);
            const float z     = hn + pf_x + bgv;
            const float sig   = 1.f / (1.f + __expf(-z));

            outsec[idx]             = hn * z * sig;   /* out[t]            */
            hsec[idx + BD]          = hn;             /* h[t+1] (output)   */
            g_hT[nxt][d0 + edl][eb] = hn;             /* h[t+1] transposed */
            hp = hn;
        }
        pf_v = nv; pf_d = nd; pf_x = nx;
        idx += BD;

        /* ---- publish: all 8 h rows of this CTA written -> arrive ---- */
        __syncthreads();                     /* joins epilogue + sRed guard */
        if (t + 1 < TT && tid == 0) {
            __threadfence();
            atomicAdd(&g_wf[(cta >> 4) * 64], 1u);
        }
    }
}

extern "C" void kernel_launch(void* const* d_in, const int* in_sizes, int n_in,
                              void* d_out, int out_size)
{
    const float* x   = (const float*)d_in[0];
    const float* h0  = (const float*)d_in[1];
    const float* Rh  = (const float*)d_in[2];
    const float* Rx  = (const float*)d_in[3];
    const float* Rd  = (const float*)d_in[4];
    const float* Wdl = (const float*)d_in[5];
    const float* b   = (const float*)d_in[6];
    const float* bd  = (const float*)d_in[7];
    const float* bgt = (const float*)d_in[8];

    float* outsec = (float*)d_out;          /* [T,B,D] outputs         */
    float* hsec   = outsec + (size_t)TBD;   /* [T+1,B,D] hidden states */

    cudaFuncSetAttribute(rec_kernel,
                         cudaFuncAttributeMaxDynamicSharedMemorySize,
                         (int)SMEM_REC);

    /* h[0] = h0 */
    cudaMemcpyAsync(hsec, h0, (size_t)BD * sizeof(float),
                    cudaMemcpyDeviceToDevice, 0);

    /* big input GEMM: stash xRx into out[t], xWd into h[t+1] */
    dim3 pgrid(TT * BB / BM, 2 * DD / BN);  /* (512, 32) */
    pre_gemm_kernel<<<pgrid, 256>>>(x, Rx, Wdl, b, bd, outsec, hsec);

    /* single persistent kernel for the whole scan */
    rec_kernel<<<128, 256, SMEM_REC>>>(x, h0, Rh, Rd, bgt, outsec, hsec);
}